// round 5
// baseline (speedup 1.0000x reference)
#include <cuda_runtime.h>
#include <cuda_bf16.h>

typedef unsigned int u32;

#define M_TOT   16384          // 16 * 32 * 32 tiles
#define NAB     36
#define PL      ((size_t)M_TOT * 64)    // V plane elements

// Scratch (__device__ globals; no allocation allowed)
__device__ __nv_bfloat16 g_Vh[NAB * PL];       // V hi plane [ab][m][ci]
__device__ __nv_bfloat16 g_Vl[NAB * PL];       // V lo plane
__device__ __nv_bfloat16 g_Wh[NAB * 64 * 64];  // W hi [ab][co][ci]
__device__ __nv_bfloat16 g_Wl[NAB * 64 * 64];  // W lo

__device__ __forceinline__ u32 smem_u32(const void* p) {
    u32 a;
    asm("{ .reg .u64 t; cvta.to.shared.u64 t, %1; cvt.u32.u64 %0, t; }" : "=r"(a) : "l"(p));
    return a;
}
__device__ __forceinline__ void cp16(u32 dst, const void* src) {
    asm volatile("cp.async.cg.shared.global [%0], [%1], 16;" :: "r"(dst), "l"(src) : "memory");
}
__device__ __forceinline__ void mma16(float* d, u32 a0, u32 a1, u32 a2, u32 a3,
                                      u32 b0, u32 b1) {
    asm volatile(
        "mma.sync.aligned.m16n8k16.row.col.f32.bf16.bf16.f32 "
        "{%0,%1,%2,%3}, {%4,%5,%6,%7}, {%8,%9}, {%0,%1,%2,%3};"
        : "+f"(d[0]), "+f"(d[1]), "+f"(d[2]), "+f"(d[3])
        : "r"(a0), "r"(a1), "r"(a2), "r"(a3), "r"(b0), "r"(b1));
}

// ---------------------------------------------------------------------------
// K1: weight prep  weight[co][ci][ab] -> (bf16 hi, lo) [ab][co][ci]
// ---------------------------------------------------------------------------
__global__ __launch_bounds__(256) void wt_kernel(const float* __restrict__ w) {
    int idx = blockIdx.x * 256 + threadIdx.x;      // ab*4096 + co*64 + ci
    if (idx >= NAB * 64 * 64) return;
    int ci = idx & 63;
    int co = (idx >> 6) & 63;
    int ab = idx >> 12;
    float v = w[(co * 64 + ci) * 36 + ab];
    __nv_bfloat16 h = __float2bfloat16(v);
    __nv_bfloat16 l = __float2bfloat16(v - __bfloat162float(h));
    g_Wh[idx] = h;
    g_Wl[idx] = l;
}

// ---------------------------------------------------------------------------
// K2: input transform -> (bf16 hi, lo) V[ab][m][ci]
// CTA = (n, p, 8 q-blocks of 4 tiles) x 64 ci.  256 threads.
// ---------------------------------------------------------------------------
__global__ __launch_bounds__(256) void in_transform(const float* __restrict__ x) {
    __shared__ float sx[64 * 109];   // [ci][h*18+w], pitch 109

    int b  = blockIdx.x;
    int qb = b & 7;
    int p  = (b >> 3) & 31;
    int n  = b >> 8;
    int tid = threadIdx.x;

    int h0 = p * 4 - 1;
    int w0 = qb * 16 - 1;

#pragma unroll
    for (int k = 0; k < 27; k++) {
        int f = k * 256 + tid;
        int wl = f % 18;
        int u  = f / 18;
        int hl = u % 6;
        int ci = u / 6;
        int gh = h0 + hl, gw = w0 + wl;
        float val = 0.0f;
        if ((unsigned)gh < 128u && (unsigned)gw < 128u)
            val = x[((size_t)(n * 64 + ci) * 128 + gh) * 128 + gw];
        sx[ci * 109 + hl * 18 + wl] = val;
    }
    __syncthreads();

    int ci = tid & 63;
    int qt = tid >> 6;
    const float* dp = &sx[ci * 109 + qt * 4];

    float d[6][6];
#pragma unroll
    for (int i = 0; i < 6; i++)
#pragma unroll
        for (int j = 0; j < 6; j++)
            d[i][j] = dp[i * 18 + j];

    float t[6][6];
#pragma unroll
    for (int j = 0; j < 6; j++) {
        t[0][j] =  4.0f * d[0][j] - 5.0f * d[2][j] + d[4][j];
        t[1][j] = -4.0f * d[1][j] - 4.0f * d[2][j] + d[3][j] + d[4][j];
        t[2][j] =  4.0f * d[1][j] - 4.0f * d[2][j] - d[3][j] + d[4][j];
        t[3][j] = -2.0f * d[1][j] - 1.0f * d[2][j] + 2.0f * d[3][j] + d[4][j];
        t[4][j] =  2.0f * d[1][j] - 1.0f * d[2][j] - 2.0f * d[3][j] + d[4][j];
        t[5][j] =  4.0f * d[1][j] - 5.0f * d[3][j] + d[5][j];
    }

    int m = n * 1024 + p * 32 + qb * 4 + qt;
    size_t base = (size_t)m * 64 + ci;
#pragma unroll
    for (int a = 0; a < 6; a++) {
        float v[6];
        v[0] =  4.0f * t[a][0] - 5.0f * t[a][2] + t[a][4];
        v[1] = -4.0f * t[a][1] - 4.0f * t[a][2] + t[a][3] + t[a][4];
        v[2] =  4.0f * t[a][1] - 4.0f * t[a][2] - t[a][3] + t[a][4];
        v[3] = -2.0f * t[a][1] - 1.0f * t[a][2] + 2.0f * t[a][3] + t[a][4];
        v[4] =  2.0f * t[a][1] - 1.0f * t[a][2] - 2.0f * t[a][3] + t[a][4];
        v[5] =  4.0f * t[a][1] - 5.0f * t[a][3] + t[a][5];
#pragma unroll
        for (int bb = 0; bb < 6; bb++) {
            __nv_bfloat16 h = __float2bfloat16(v[bb]);
            __nv_bfloat16 l = __float2bfloat16(v[bb] - __bfloat162float(h));
            size_t off = (size_t)(a * 6 + bb) * PL + base;
            g_Vh[off] = h;
            g_Vl[off] = l;
        }
    }
}

// ---------------------------------------------------------------------------
// K3: fused GEMM + output transform.
// grid 512 CTAs (32 m-tiles each), 512 threads = 16 warps (2 m x 8 co).
// Loops b(0..5) x a(0..5): M_ab via bf16 3-product mma, folded into
// register Y[4][4][4] per thread through Z[x].  Writes y + bias directly.
// SMEM: double-buffered (Vh 32x72, Vl, Wh 64x72, Wl) filled by cp.async.
// ---------------------------------------------------------------------------
#define VH_OFF 0
#define VL_OFF 2304
#define WH_OFF 4608
#define WL_OFF 9216
#define BUF_E  13824                 // bf16 elems per buffer
#define GSM_TOTAL (2 * BUF_E * 2)    // 55296 bytes

__global__ __launch_bounds__(512, 1) void gemm_kernel(const float* __restrict__ bias,
                                                      float* __restrict__ y) {
    extern __shared__ __nv_bfloat16 sm[];
    const int tid = threadIdx.x;
    const int m0 = blockIdx.x * 32;
    const u32 sb0 = smem_u32(sm);

    // ---- cp.async fill of one (a,b) plane pair into buffer (idx&1) ----
    auto issue_fill = [&](int idx) {
        int a = idx % 6, b = idx / 6;
        int plane = a * 6 + b;
        u32 sb = sb0 + (u32)(idx & 1) * (BUF_E * 2);
        const __nv_bfloat16* vh = g_Vh + (size_t)plane * PL + (size_t)m0 * 64;
        const __nv_bfloat16* vl = g_Vl + (size_t)plane * PL + (size_t)m0 * 64;
        const __nv_bfloat16* wh = g_Wh + plane * 4096;
        const __nv_bfloat16* wl = g_Wl + plane * 4096;
#pragma unroll
        for (int i = 0; i < 3; i++) {
            int t = tid + i * 512;           // 0..1535 tasks of 16B
            if (t < 512) {
                int pl = t >> 8, r = (t >> 3) & 31, c = t & 7;
                const __nv_bfloat16* src = (pl ? vl : vh) + r * 64 + c * 8;
                u32 dst = sb + (u32)((pl ? VL_OFF : VH_OFF) + r * 72 + c * 8) * 2;
                cp16(dst, src);
            } else {
                int t2 = t - 512;
                int pl = t2 >> 9, r = (t2 >> 3) & 63, c = t2 & 7;
                const __nv_bfloat16* src = (pl ? wl : wh) + r * 64 + c * 8;
                u32 dst = sb + (u32)((pl ? WL_OFF : WH_OFF) + r * 72 + c * 8) * 2;
                cp16(dst, src);
            }
        }
        asm volatile("cp.async.commit_group;" ::: "memory");
    };

    const int wid = tid >> 5, lane = tid & 31;
    const int g = lane >> 2, t4 = lane & 3;
    const int mw = wid >> 3;           // 0,1 : m-halves of 16
    const int n0 = (wid & 7) * 8;      // co base
    const int rA0 = mw * 16 + g;
    const int rA1 = rA0 + 8;
    const int cB  = n0 + g;

    float accY[4][4][4];               // [elem][x][y]
#pragma unroll
    for (int e = 0; e < 4; e++)
#pragma unroll
        for (int xx = 0; xx < 4; xx++)
#pragma unroll
            for (int yy = 0; yy < 4; yy++) accY[e][xx][yy] = 0.0f;

    issue_fill(0);

    for (int b = 0; b < 6; b++) {
        float Z[4][4];                 // [elem][x]
#pragma unroll
        for (int e = 0; e < 4; e++)
#pragma unroll
            for (int xx = 0; xx < 4; xx++) Z[e][xx] = 0.0f;

#pragma unroll
        for (int a = 0; a < 6; a++) {
            int idx = b * 6 + a;
            if (idx + 1 < 36) issue_fill(idx + 1);
            if (idx < 35) asm volatile("cp.async.wait_group 1;" ::: "memory");
            else          asm volatile("cp.async.wait_group 0;" ::: "memory");
            __syncthreads();

            const __nv_bfloat16* B = sm + (size_t)(a & 1) * BUF_E;
            const __nv_bfloat16* Vh = B + VH_OFF;
            const __nv_bfloat16* Vl = B + VL_OFF;
            const __nv_bfloat16* Wh = B + WH_OFF;
            const __nv_bfloat16* Wl = B + WL_OFF;

            float d1[4] = {0, 0, 0, 0};    // hi*hi
            float d2[4] = {0, 0, 0, 0};    // hi*lo + lo*hi
#pragma unroll
            for (int ks = 0; ks < 4; ks++) {
                int kc = ks * 16 + 2 * t4;
                u32 ah0 = *(const u32*)&Vh[rA0 * 72 + kc];
                u32 ah1 = *(const u32*)&Vh[rA1 * 72 + kc];
                u32 ah2 = *(const u32*)&Vh[rA0 * 72 + kc + 8];
                u32 ah3 = *(const u32*)&Vh[rA1 * 72 + kc + 8];
                u32 al0 = *(const u32*)&Vl[rA0 * 72 + kc];
                u32 al1 = *(const u32*)&Vl[rA1 * 72 + kc];
                u32 al2 = *(const u32*)&Vl[rA0 * 72 + kc + 8];
                u32 al3 = *(const u32*)&Vl[rA1 * 72 + kc + 8];
                u32 bh0 = *(const u32*)&Wh[cB * 72 + kc];
                u32 bh1 = *(const u32*)&Wh[cB * 72 + kc + 8];
                u32 bl0 = *(const u32*)&Wl[cB * 72 + kc];
                u32 bl1 = *(const u32*)&Wl[cB * 72 + kc + 8];
                mma16(d1, ah0, ah1, ah2, ah3, bh0, bh1);
                mma16(d2, ah0, ah1, ah2, ah3, bl0, bl1);
                mma16(d2, al0, al1, al2, al3, bh0, bh1);
            }
            __syncthreads();   // done reading this buffer (refilled at idx+2)

            // fold M_ab into Z with AT column a (compile-time coefficients)
#pragma unroll
            for (int e = 0; e < 4; e++) {
                float dd = d1[e] + d2[e];
                if (a == 0) {
                    Z[e][0] += dd;
                } else if (a == 1) {
                    Z[e][0] += dd; Z[e][1] += dd; Z[e][2] += dd; Z[e][3] += dd;
                } else if (a == 2) {
                    Z[e][0] += dd; Z[e][1] -= dd; Z[e][2] += dd; Z[e][3] -= dd;
                } else if (a == 3) {
                    Z[e][0] += dd; Z[e][1] += 2.0f * dd;
                    Z[e][2] += 4.0f * dd; Z[e][3] += 8.0f * dd;
                } else if (a == 4) {
                    Z[e][0] += dd; Z[e][1] -= 2.0f * dd;
                    Z[e][2] += 4.0f * dd; Z[e][3] -= 8.0f * dd;
                } else {
                    Z[e][3] += dd;
                }
            }
        }

        // fold Z into Y with AT column b (runtime b, small table)
        const float CB0[6] = {1, 1, 1, 1, 1, 0};
        const float CB1[6] = {0, 1, -1, 2, -2, 0};
        const float CB2[6] = {0, 1, 1, 4, 4, 0};
        const float CB3[6] = {0, 1, -1, 8, -8, 1};
        float c0 = CB0[b], c1 = CB1[b], c2 = CB2[b], c3 = CB3[b];
#pragma unroll
        for (int e = 0; e < 4; e++)
#pragma unroll
            for (int xx = 0; xx < 4; xx++) {
                float z = Z[e][xx];
                accY[e][xx][0] += z * c0;
                accY[e][xx][1] += z * c1;
                accY[e][xx][2] += z * c2;
                accY[e][xx][3] += z * c3;
            }
    }

    // ---- epilogue: bias + direct y stores ----
    float bv0 = __ldg(&bias[n0 + 2 * t4]);
    float bv1 = __ldg(&bias[n0 + 2 * t4 + 1]);
#pragma unroll
    for (int e = 0; e < 4; e++) {
        int co = n0 + 2 * t4 + (e & 1);
        float bv = (e & 1) ? bv1 : bv0;
        int lrow = mw * 16 + g + ((e >> 1) ? 8 : 0);
        int m = m0 + lrow;
        int n = m >> 10;
        int p = (m >> 5) & 31;
        int q = m & 31;
        float* yb = y + (((size_t)(n * 64 + co) * 128) + p * 4) * 128 + q * 4;
#pragma unroll
        for (int xx = 0; xx < 4; xx++) {
            float4 st = make_float4(accY[e][xx][0] + bv, accY[e][xx][1] + bv,
                                    accY[e][xx][2] + bv, accY[e][xx][3] + bv);
            *(float4*)(yb + xx * 128) = st;
        }
    }
}

// ---------------------------------------------------------------------------
extern "C" void kernel_launch(void* const* d_in, const int* in_sizes, int n_in,
                              void* d_out, int out_size) {
    const float* x = (const float*)d_in[0];   // (16, 64, 128, 128) f32
    const float* w = (const float*)d_in[1];   // (64, 64, 6, 6) f32
    const float* b = (const float*)d_in[2];   // (64,) f32
    float* y = (float*)d_out;                 // (16, 64, 128, 128) f32

    cudaFuncSetAttribute(gemm_kernel, cudaFuncAttributeMaxDynamicSharedMemorySize,
                         GSM_TOTAL);

    wt_kernel<<<(NAB * 64 * 64 + 255) / 256, 256>>>(w);
    in_transform<<<4096, 256>>>(x);
    gemm_kernel<<<512, 512, GSM_TOTAL>>>(b, y);
}

// round 6
// speedup vs baseline: 1.3825x; 1.3825x over previous
#include <cuda_runtime.h>
#include <cuda_fp16.h>

typedef unsigned int u32;

#define M_TOT   16384          // 16 * 32 * 32 tiles
#define NAB     36
#define PL      ((size_t)M_TOT * 64)

// Scratch (__device__ globals; no allocation allowed)
__device__ __align__(256) __half g_V[NAB * PL];        // V fp16 [ab][m][ci]
__device__ __align__(256) __half g_Wh[NAB * 64 * 64];  // W hi [ab][co][ci]
__device__ __align__(256) __half g_Wl[NAB * 64 * 64];  // (W - Whi) * 2048

__device__ __forceinline__ u32 smem_u32(const void* p) {
    u32 a;
    asm("{ .reg .u64 t; cvta.to.shared.u64 t, %1; cvt.u32.u64 %0, t; }" : "=r"(a) : "l"(p));
    return a;
}
__device__ __forceinline__ void cp16(u32 dst, const void* src) {
    asm volatile("cp.async.cg.shared.global [%0], [%1], 16;" :: "r"(dst), "l"(src) : "memory");
}
__device__ __forceinline__ void ldmx4(u32* r, u32 addr) {
    asm volatile("ldmatrix.sync.aligned.m8n8.x4.shared.b16 {%0,%1,%2,%3}, [%4];"
        : "=r"(r[0]), "=r"(r[1]), "=r"(r[2]), "=r"(r[3]) : "r"(addr));
}
__device__ __forceinline__ void ldmx2(u32* r, u32 addr) {
    asm volatile("ldmatrix.sync.aligned.m8n8.x2.shared.b16 {%0,%1}, [%2];"
        : "=r"(r[0]), "=r"(r[1]) : "r"(addr));
}
__device__ __forceinline__ void mma16f(float* d, const u32* a, const u32* b) {
    asm volatile(
        "mma.sync.aligned.m16n8k16.row.col.f32.f16.f16.f32 "
        "{%0,%1,%2,%3}, {%4,%5,%6,%7}, {%8,%9}, {%0,%1,%2,%3};"
        : "+f"(d[0]), "+f"(d[1]), "+f"(d[2]), "+f"(d[3])
        : "r"(a[0]), "r"(a[1]), "r"(a[2]), "r"(a[3]), "r"(b[0]), "r"(b[1]));
}

// ---------------------------------------------------------------------------
// K1: weight prep  weight[co][ci][ab] -> fp16 hi + scaled-lo [ab][co][ci]
// ---------------------------------------------------------------------------
__global__ __launch_bounds__(256) void wt_kernel(const float* __restrict__ w) {
    int idx = blockIdx.x * 256 + threadIdx.x;      // ab*4096 + co*64 + ci
    if (idx >= NAB * 64 * 64) return;
    int ci = idx & 63;
    int co = (idx >> 6) & 63;
    int ab = idx >> 12;
    float v = w[(co * 64 + ci) * 36 + ab];
    __half h = __float2half_rn(v);
    __half l = __float2half_rn((v - __half2float(h)) * 2048.0f);
    g_Wh[idx] = h;
    g_Wl[idx] = l;
}

// ---------------------------------------------------------------------------
// K2: input transform -> fp16 V[ab][m][ci]
// ---------------------------------------------------------------------------
__global__ __launch_bounds__(256) void in_transform(const float* __restrict__ x) {
    __shared__ float sx[64 * 109];   // [ci][h*18+w], pitch 109

    int b  = blockIdx.x;
    int qb = b & 7;
    int p  = (b >> 3) & 31;
    int n  = b >> 8;
    int tid = threadIdx.x;

    int h0 = p * 4 - 1;
    int w0 = qb * 16 - 1;

#pragma unroll
    for (int k = 0; k < 27; k++) {
        int f = k * 256 + tid;
        int wl = f % 18;
        int u  = f / 18;
        int hl = u % 6;
        int ci = u / 6;
        int gh = h0 + hl, gw = w0 + wl;
        float val = 0.0f;
        if ((unsigned)gh < 128u && (unsigned)gw < 128u)
            val = x[((size_t)(n * 64 + ci) * 128 + gh) * 128 + gw];
        sx[ci * 109 + hl * 18 + wl] = val;
    }
    __syncthreads();

    int ci = tid & 63;
    int qt = tid >> 6;
    const float* dp = &sx[ci * 109 + qt * 4];

    float d[6][6];
#pragma unroll
    for (int i = 0; i < 6; i++)
#pragma unroll
        for (int j = 0; j < 6; j++)
            d[i][j] = dp[i * 18 + j];

    float t[6][6];
#pragma unroll
    for (int j = 0; j < 6; j++) {
        t[0][j] =  4.0f * d[0][j] - 5.0f * d[2][j] + d[4][j];
        t[1][j] = -4.0f * d[1][j] - 4.0f * d[2][j] + d[3][j] + d[4][j];
        t[2][j] =  4.0f * d[1][j] - 4.0f * d[2][j] - d[3][j] + d[4][j];
        t[3][j] = -2.0f * d[1][j] - 1.0f * d[2][j] + 2.0f * d[3][j] + d[4][j];
        t[4][j] =  2.0f * d[1][j] - 1.0f * d[2][j] - 2.0f * d[3][j] + d[4][j];
        t[5][j] =  4.0f * d[1][j] - 5.0f * d[3][j] + d[5][j];
    }

    int m = n * 1024 + p * 32 + qb * 4 + qt;
    size_t base = (size_t)m * 64 + ci;
#pragma unroll
    for (int a = 0; a < 6; a++) {
        float v[6];
        v[0] =  4.0f * t[a][0] - 5.0f * t[a][2] + t[a][4];
        v[1] = -4.0f * t[a][1] - 4.0f * t[a][2] + t[a][3] + t[a][4];
        v[2] =  4.0f * t[a][1] - 4.0f * t[a][2] - t[a][3] + t[a][4];
        v[3] = -2.0f * t[a][1] - 1.0f * t[a][2] + 2.0f * t[a][3] + t[a][4];
        v[4] =  2.0f * t[a][1] - 1.0f * t[a][2] - 2.0f * t[a][3] + t[a][4];
        v[5] =  4.0f * t[a][1] - 5.0f * t[a][3] + t[a][5];
#pragma unroll
        for (int bb = 0; bb < 6; bb++)
            g_V[(size_t)(a * 6 + bb) * PL + base] = __float2half_rn(v[bb]);
    }
}

// ---------------------------------------------------------------------------
// K3: fused GEMM + output transform.
// grid 512 CTAs (32 m-tiles), 256 threads = 8 warps (2 mw x 4 nw),
// warp tile 16m x 16co.  b-outer/a-inner over 36 planes; per-plane
// M_ab = V * W^T via fp16 mma (V single + W hi/lo), folded into
// register Y through Z.  Direct y stores + bias.
// ---------------------------------------------------------------------------
#define PITCH   72                       // halfs per smem row (conflict-free)
#define V_OFF   0
#define WH_OFF  (32 * PITCH)             // 2304
#define WL_OFF  (WH_OFF + 64 * PITCH)    // 6912
#define BUF_E   (WL_OFF + 64 * PITCH)    // 11520 halfs
#define GSM_TOTAL (2 * BUF_E * 2)        // 46080 bytes

__global__ __launch_bounds__(256, 1) void gemm_kernel(const float* __restrict__ bias,
                                                      float* __restrict__ y) {
    extern __shared__ __half sm[];
    const int tid = threadIdx.x;
    const int m0 = blockIdx.x * 32;
    const u32 sb0 = smem_u32(sm);

    auto issue_fill = [&](int idx) {
        int a = idx % 6, b = idx / 6;
        int plane = a * 6 + b;
        u32 sb = sb0 + (u32)(idx & 1) * (BUF_E * 2);
        const __half* vp = g_V + (size_t)plane * PL + (size_t)m0 * 64;
        const __half* wh = g_Wh + plane * 4096;
        const __half* wl = g_Wl + plane * 4096;
#pragma unroll
        for (int i = 0; i < 5; i++) {
            int t = tid + i * 256;               // 0..1279 tasks of 16 B
            if (t < 256) {
                int r = t >> 3, c = t & 7;
                cp16(sb + (u32)(V_OFF * 2 + r * 144 + c * 16), vp + r * 64 + c * 8);
            } else if (t < 768) {
                int t2 = t - 256;
                int r = t2 >> 3, c = t2 & 7;
                cp16(sb + (u32)(WH_OFF * 2 + r * 144 + c * 16), wh + r * 64 + c * 8);
            } else {
                int t3 = t - 768;
                int r = t3 >> 3, c = t3 & 7;
                cp16(sb + (u32)(WL_OFF * 2 + r * 144 + c * 16), wl + r * 64 + c * 8);
            }
        }
        asm volatile("cp.async.commit_group;" ::: "memory");
    };

    const int wid = tid >> 5, lane = tid & 31;
    const int g = lane >> 2, t4 = lane & 3;
    const int mw = wid & 1;            // 2 m-warps x 16 rows
    const int nq = wid >> 1;           // 4 co-warps x 16 cols
    const int warpM = mw * 16;
    const int warpN = nq * 16;

    // ldmatrix per-lane byte offsets within a buffer
    const u32 aOff = (u32)(V_OFF * 2 + (warpM + (lane & 15)) * 144 + (lane >> 4) * 16);
    const int bl = lane & 15;
    const u32 bRel = (u32)((warpN + (bl & 7)) * 144 + ((bl >> 3) & 1) * 16);
    const u32 bhOff = (u32)(WH_OFF * 2) + bRel;
    const u32 blOff = (u32)(WL_OFF * 2) + bRel;

    float accY[8][4][4];
#pragma unroll
    for (int e = 0; e < 8; e++)
#pragma unroll
        for (int xx = 0; xx < 4; xx++)
#pragma unroll
            for (int yy = 0; yy < 4; yy++) accY[e][xx][yy] = 0.0f;

    issue_fill(0);

    for (int b = 0; b < 6; b++) {
        float Z[8][4];
#pragma unroll
        for (int e = 0; e < 8; e++)
#pragma unroll
            for (int xx = 0; xx < 4; xx++) Z[e][xx] = 0.0f;

#pragma unroll
        for (int a = 0; a < 6; a++) {
            int idx = b * 6 + a;
            if (idx + 1 < 36) issue_fill(idx + 1);
            if (idx < 35) asm volatile("cp.async.wait_group 1;" ::: "memory");
            else          asm volatile("cp.async.wait_group 0;" ::: "memory");
            __syncthreads();

            u32 base = sb0 + (u32)(idx & 1) * (BUF_E * 2);

            float d1[2][4], d2[2][4];
#pragma unroll
            for (int j = 0; j < 2; j++)
#pragma unroll
                for (int r = 0; r < 4; r++) { d1[j][r] = 0.0f; d2[j][r] = 0.0f; }

#pragma unroll
            for (int ks = 0; ks < 4; ks++) {
                u32 av[4];
                ldmx4(av, base + aOff + ks * 32);
#pragma unroll
                for (int j = 0; j < 2; j++) {
                    u32 bh[2], blr[2];
                    ldmx2(bh,  base + bhOff + j * (8 * 144) + ks * 32);
                    ldmx2(blr, base + blOff + j * (8 * 144) + ks * 32);
                    mma16f(d1[j], av, bh);
                    mma16f(d2[j], av, blr);
                }
            }
            __syncthreads();   // done reading this buffer (refilled at idx+2)

            // fold M_ab into Z with AT column a (compile-time coefficients)
#pragma unroll
            for (int j = 0; j < 2; j++)
#pragma unroll
                for (int r = 0; r < 4; r++) {
                    int e = j * 4 + r;
                    float dd = fmaf(d2[j][r], 4.8828125e-4f, d1[j][r]);
                    if (a == 0) {
                        Z[e][0] += dd;
                    } else if (a == 1) {
                        Z[e][0] += dd; Z[e][1] += dd; Z[e][2] += dd; Z[e][3] += dd;
                    } else if (a == 2) {
                        Z[e][0] += dd; Z[e][1] -= dd; Z[e][2] += dd; Z[e][3] -= dd;
                    } else if (a == 3) {
                        Z[e][0] += dd; Z[e][1] += 2.0f * dd;
                        Z[e][2] += 4.0f * dd; Z[e][3] += 8.0f * dd;
                    } else if (a == 4) {
                        Z[e][0] += dd; Z[e][1] -= 2.0f * dd;
                        Z[e][2] += 4.0f * dd; Z[e][3] -= 8.0f * dd;
                    } else {
                        Z[e][3] += dd;
                    }
                }
        }

        // fold Z into Y with AT column b
        float c0 = (b == 5) ? 0.0f : 1.0f;
        if (b == 0) c0 = 1.0f;
        float c1, c2, c3;
        switch (b) {
            case 0:  c0 = 1; c1 = 0;  c2 = 0; c3 = 0;  break;
            case 1:  c0 = 1; c1 = 1;  c2 = 1; c3 = 1;  break;
            case 2:  c0 = 1; c1 = -1; c2 = 1; c3 = -1; break;
            case 3:  c0 = 1; c1 = 2;  c2 = 4; c3 = 8;  break;
            case 4:  c0 = 1; c1 = -2; c2 = 4; c3 = -8; break;
            default: c0 = 0; c1 = 0;  c2 = 0; c3 = 1;  break;
        }
#pragma unroll
        for (int e = 0; e < 8; e++)
#pragma unroll
            for (int xx = 0; xx < 4; xx++) {
                float z = Z[e][xx];
                accY[e][xx][0] += z * c0;
                accY[e][xx][1] += z * c1;
                accY[e][xx][2] += z * c2;
                accY[e][xx][3] += z * c3;
            }
    }

    // ---- epilogue: bias + direct y stores ----
#pragma unroll
    for (int e = 0; e < 8; e++) {
        int j = e >> 2, r = e & 3;
        int co = warpN + j * 8 + 2 * t4 + (r & 1);
        int mrow = warpM + g + (r >> 1) * 8;
        float bv = __ldg(&bias[co]);
        int m = m0 + mrow;
        int n = m >> 10;
        int p = (m >> 5) & 31;
        int q = m & 31;
        float* yb = y + (((size_t)(n * 64 + co) * 128) + p * 4) * 128 + q * 4;
#pragma unroll
        for (int xx = 0; xx < 4; xx++) {
            float4 st = make_float4(accY[e][xx][0] + bv, accY[e][xx][1] + bv,
                                    accY[e][xx][2] + bv, accY[e][xx][3] + bv);
            *(float4*)(yb + xx * 128) = st;
        }
    }
}

// ---------------------------------------------------------------------------
extern "C" void kernel_launch(void* const* d_in, const int* in_sizes, int n_in,
                              void* d_out, int out_size) {
    const float* x = (const float*)d_in[0];   // (16, 64, 128, 128) f32
    const float* w = (const float*)d_in[1];   // (64, 64, 6, 6) f32
    const float* b = (const float*)d_in[2];   // (64,) f32
    float* y = (float*)d_out;                 // (16, 64, 128, 128) f32

    cudaFuncSetAttribute(gemm_kernel, cudaFuncAttributeMaxDynamicSharedMemorySize,
                         GSM_TOTAL);

    wt_kernel<<<(NAB * 64 * 64 + 255) / 256, 256>>>(w);
    in_transform<<<4096, 256>>>(x);
    gemm_kernel<<<512, 256, GSM_TOTAL>>>(b, y);
}

// round 7
// speedup vs baseline: 1.6265x; 1.1765x over previous
#include <cuda_runtime.h>
#include <cuda_fp16.h>

typedef unsigned int u32;

#define M_TOT   16384          // 16 * 32 * 32 tiles
#define NAB     36
#define PL      ((size_t)M_TOT * 64)

// Scratch (__device__ globals; no allocation allowed)
__device__ __align__(256) __half g_V[NAB * PL];       // V fp16 [ab][m][ci]
__device__ __align__(256) __half g_W[NAB * 64 * 64];  // W fp16 [ab][co][ci]

__device__ __forceinline__ u32 smem_u32(const void* p) {
    u32 a;
    asm("{ .reg .u64 t; cvta.to.shared.u64 t, %1; cvt.u32.u64 %0, t; }" : "=r"(a) : "l"(p));
    return a;
}
__device__ __forceinline__ void cp16(u32 dst, const void* src) {
    asm volatile("cp.async.cg.shared.global [%0], [%1], 16;" :: "r"(dst), "l"(src) : "memory");
}
__device__ __forceinline__ void ldmx4(u32* r, u32 addr) {
    asm volatile("ldmatrix.sync.aligned.m8n8.x4.shared.b16 {%0,%1,%2,%3}, [%4];"
        : "=r"(r[0]), "=r"(r[1]), "=r"(r[2]), "=r"(r[3]) : "r"(addr));
}
__device__ __forceinline__ void ldmx2(u32* r, u32 addr) {
    asm volatile("ldmatrix.sync.aligned.m8n8.x2.shared.b16 {%0,%1}, [%2];"
        : "=r"(r[0]), "=r"(r[1]) : "r"(addr));
}
__device__ __forceinline__ void mma16f(float* d, const u32* a, const u32* b) {
    asm volatile(
        "mma.sync.aligned.m16n8k16.row.col.f32.f16.f16.f32 "
        "{%0,%1,%2,%3}, {%4,%5,%6,%7}, {%8,%9}, {%0,%1,%2,%3};"
        : "+f"(d[0]), "+f"(d[1]), "+f"(d[2]), "+f"(d[3])
        : "r"(a[0]), "r"(a[1]), "r"(a[2]), "r"(a[3]), "r"(b[0]), "r"(b[1]));
}

// ---------------------------------------------------------------------------
// K1: weight prep  weight[co][ci][ab] -> fp16 [ab][co][ci]
// ---------------------------------------------------------------------------
__global__ __launch_bounds__(256) void wt_kernel(const float* __restrict__ w) {
    int idx = blockIdx.x * 256 + threadIdx.x;      // ab*4096 + co*64 + ci
    if (idx >= NAB * 64 * 64) return;
    int ci = idx & 63;
    int co = (idx >> 6) & 63;
    int ab = idx >> 12;
    g_W[idx] = __float2half_rn(w[(co * 64 + ci) * 36 + ab]);
}

// ---------------------------------------------------------------------------
// K2: input transform -> fp16 V[ab][m][ci]
// ---------------------------------------------------------------------------
__global__ __launch_bounds__(256) void in_transform(const float* __restrict__ x) {
    __shared__ float sx[64 * 109];   // [ci][h*18+w], pitch 109

    int b  = blockIdx.x;
    int qb = b & 7;
    int p  = (b >> 3) & 31;
    int n  = b >> 8;
    int tid = threadIdx.x;

    int h0 = p * 4 - 1;
    int w0 = qb * 16 - 1;

#pragma unroll
    for (int k = 0; k < 27; k++) {
        int f = k * 256 + tid;
        int wl = f % 18;
        int u  = f / 18;
        int hl = u % 6;
        int ci = u / 6;
        int gh = h0 + hl, gw = w0 + wl;
        float val = 0.0f;
        if ((unsigned)gh < 128u && (unsigned)gw < 128u)
            val = x[((size_t)(n * 64 + ci) * 128 + gh) * 128 + gw];
        sx[ci * 109 + hl * 18 + wl] = val;
    }
    __syncthreads();

    int ci = tid & 63;
    int qt = tid >> 6;
    const float* dp = &sx[ci * 109 + qt * 4];

    float d[6][6];
#pragma unroll
    for (int i = 0; i < 6; i++)
#pragma unroll
        for (int j = 0; j < 6; j++)
            d[i][j] = dp[i * 18 + j];

    float t[6][6];
#pragma unroll
    for (int j = 0; j < 6; j++) {
        t[0][j] =  4.0f * d[0][j] - 5.0f * d[2][j] + d[4][j];
        t[1][j] = -4.0f * d[1][j] - 4.0f * d[2][j] + d[3][j] + d[4][j];
        t[2][j] =  4.0f * d[1][j] - 4.0f * d[2][j] - d[3][j] + d[4][j];
        t[3][j] = -2.0f * d[1][j] - 1.0f * d[2][j] + 2.0f * d[3][j] + d[4][j];
        t[4][j] =  2.0f * d[1][j] - 1.0f * d[2][j] - 2.0f * d[3][j] + d[4][j];
        t[5][j] =  4.0f * d[1][j] - 5.0f * d[3][j] + d[5][j];
    }

    int m = n * 1024 + p * 32 + qb * 4 + qt;
    size_t base = (size_t)m * 64 + ci;
#pragma unroll
    for (int a = 0; a < 6; a++) {
        float v[6];
        v[0] =  4.0f * t[a][0] - 5.0f * t[a][2] + t[a][4];
        v[1] = -4.0f * t[a][1] - 4.0f * t[a][2] + t[a][3] + t[a][4];
        v[2] =  4.0f * t[a][1] - 4.0f * t[a][2] - t[a][3] + t[a][4];
        v[3] = -2.0f * t[a][1] - 1.0f * t[a][2] + 2.0f * t[a][3] + t[a][4];
        v[4] =  2.0f * t[a][1] - 1.0f * t[a][2] - 2.0f * t[a][3] + t[a][4];
        v[5] =  4.0f * t[a][1] - 5.0f * t[a][3] + t[a][5];
#pragma unroll
        for (int bb = 0; bb < 6; bb++)
            g_V[(size_t)(a * 6 + bb) * PL + base] = __float2half_rn(v[bb]);
    }
}

// ---------------------------------------------------------------------------
// K3: fused GEMM + output transform.
// grid 512 CTAs (32 m-tiles), 256 threads = 8 warps (2 mw x 4 nw),
// warp tile 16m x 16co.  b-outer/a-inner over 36 planes; per-plane
// M_ab = V * W^T via single fp16 mma, folded into register Y through Z.
// 3-stage cp.async pipeline, one __syncthreads per plane.
// ---------------------------------------------------------------------------
#define PITCH   72                       // halfs per smem row
#define V_OFF   0
#define W_OFF   (32 * PITCH)             // 2304
#define BUF_E   (W_OFF + 64 * PITCH)     // 6912 halfs = 13824 B
#define NSTAGE  3
#define GSM_TOTAL (NSTAGE * BUF_E * 2)   // 41472 bytes

__global__ __launch_bounds__(256, 1) void gemm_kernel(const float* __restrict__ bias,
                                                      float* __restrict__ y) {
    extern __shared__ __half sm[];
    const int tid = threadIdx.x;
    const int m0 = blockIdx.x * 32;
    const u32 sb0 = smem_u32(sm);

    auto issue_fill = [&](int idx) {
        int a = idx % 6, b = idx / 6;
        int plane = a * 6 + b;
        u32 sb = sb0 + (u32)(idx % NSTAGE) * (BUF_E * 2);
        const __half* vp = g_V + (size_t)plane * PL + (size_t)m0 * 64;
        const __half* wp = g_W + plane * 4096;
#pragma unroll
        for (int i = 0; i < 3; i++) {
            int t = tid + i * 256;               // 0..767 tasks of 16 B
            if (t < 256) {
                int r = t >> 3, c = t & 7;
                cp16(sb + (u32)(V_OFF * 2 + r * 144 + c * 16), vp + r * 64 + c * 8);
            } else {
                int t2 = t - 256;
                int r = t2 >> 3, c = t2 & 7;
                cp16(sb + (u32)(W_OFF * 2 + r * 144 + c * 16), wp + r * 64 + c * 8);
            }
        }
        asm volatile("cp.async.commit_group;" ::: "memory");
    };

    const int wid = tid >> 5, lane = tid & 31;
    const int g = lane >> 2, t4 = lane & 3;
    const int mw = wid & 1;            // 2 m-warps x 16 rows
    const int nq = wid >> 1;           // 4 co-warps x 16 cols
    const int warpM = mw * 16;
    const int warpN = nq * 16;

    const u32 aOff = (u32)(V_OFF * 2 + (warpM + (lane & 15)) * 144 + (lane >> 4) * 16);
    const int bl = lane & 15;
    const u32 bOff = (u32)(W_OFF * 2) + (u32)((warpN + (bl & 7)) * 144 + ((bl >> 3) & 1) * 16);

    float accY[8][4][4];
#pragma unroll
    for (int e = 0; e < 8; e++)
#pragma unroll
        for (int xx = 0; xx < 4; xx++)
#pragma unroll
            for (int yy = 0; yy < 4; yy++) accY[e][xx][yy] = 0.0f;

    issue_fill(0);
    issue_fill(1);

    for (int b = 0; b < 6; b++) {
        float Z[8][4];
#pragma unroll
        for (int e = 0; e < 8; e++)
#pragma unroll
            for (int xx = 0; xx < 4; xx++) Z[e][xx] = 0.0f;

#pragma unroll
        for (int a = 0; a < 6; a++) {
            int idx = b * 6 + a;
            if (idx < 35) asm volatile("cp.async.wait_group 1;" ::: "memory");
            else          asm volatile("cp.async.wait_group 0;" ::: "memory");
            __syncthreads();
            if (idx + 2 < 36) issue_fill(idx + 2);

            u32 base = sb0 + (u32)(idx % NSTAGE) * (BUF_E * 2);

            float d[2][4];
#pragma unroll
            for (int j = 0; j < 2; j++)
#pragma unroll
                for (int r = 0; r < 4; r++) d[j][r] = 0.0f;

#pragma unroll
            for (int ks = 0; ks < 4; ks++) {
                u32 av[4];
                ldmx4(av, base + aOff + ks * 32);
#pragma unroll
                for (int j = 0; j < 2; j++) {
                    u32 bw[2];
                    ldmx2(bw, base + bOff + j * (8 * 144) + ks * 32);
                    mma16f(d[j], av, bw);
                }
            }

            // fold M_ab into Z with AT column a (compile-time coefficients)
#pragma unroll
            for (int j = 0; j < 2; j++)
#pragma unroll
                for (int r = 0; r < 4; r++) {
                    int e = j * 4 + r;
                    float dd = d[j][r];
                    if (a == 0) {
                        Z[e][0] += dd;
                    } else if (a == 1) {
                        Z[e][0] += dd; Z[e][1] += dd; Z[e][2] += dd; Z[e][3] += dd;
                    } else if (a == 2) {
                        Z[e][0] += dd; Z[e][1] -= dd; Z[e][2] += dd; Z[e][3] -= dd;
                    } else if (a == 3) {
                        Z[e][0] += dd; Z[e][1] += 2.0f * dd;
                        Z[e][2] += 4.0f * dd; Z[e][3] += 8.0f * dd;
                    } else if (a == 4) {
                        Z[e][0] += dd; Z[e][1] -= 2.0f * dd;
                        Z[e][2] += 4.0f * dd; Z[e][3] -= 8.0f * dd;
                    } else {
                        Z[e][3] += dd;
                    }
                }
        }

        // fold Z into Y with AT column b
        float c0, c1, c2, c3;
        switch (b) {
            case 0:  c0 = 1; c1 = 0;  c2 = 0; c3 = 0;  break;
            case 1:  c0 = 1; c1 = 1;  c2 = 1; c3 = 1;  break;
            case 2:  c0 = 1; c1 = -1; c2 = 1; c3 = -1; break;
            case 3:  c0 = 1; c1 = 2;  c2 = 4; c3 = 8;  break;
            case 4:  c0 = 1; c1 = -2; c2 = 4; c3 = -8; break;
            default: c0 = 0; c1 = 0;  c2 = 0; c3 = 1;  break;
        }
#pragma unroll
        for (int e = 0; e < 8; e++)
#pragma unroll
            for (int xx = 0; xx < 4; xx++) {
                float z = Z[e][xx];
                accY[e][xx][0] += z * c0;
                accY[e][xx][1] += z * c1;
                accY[e][xx][2] += z * c2;
                accY[e][xx][3] += z * c3;
            }
    }

    // ---- epilogue: bias + direct y stores ----
#pragma unroll
    for (int e = 0; e < 8; e++) {
        int j = e >> 2, r = e & 3;
        int co = warpN + j * 8 + 2 * t4 + (r & 1);
        int mrow = warpM + g + (r >> 1) * 8;
        float bv = __ldg(&bias[co]);
        int m = m0 + mrow;
        int n = m >> 10;
        int p = (m >> 5) & 31;
        int q = m & 31;
        float* yb = y + (((size_t)(n * 64 + co) * 128) + p * 4) * 128 + q * 4;
#pragma unroll
        for (int xx = 0; xx < 4; xx++) {
            float4 st = make_float4(accY[e][xx][0] + bv, accY[e][xx][1] + bv,
                                    accY[e][xx][2] + bv, accY[e][xx][3] + bv);
            *(float4*)(yb + xx * 128) = st;
        }
    }
}

// ---------------------------------------------------------------------------
extern "C" void kernel_launch(void* const* d_in, const int* in_sizes, int n_in,
                              void* d_out, int out_size) {
    const float* x = (const float*)d_in[0];   // (16, 64, 128, 128) f32
    const float* w = (const float*)d_in[1];   // (64, 64, 6, 6) f32
    const float* b = (const float*)d_in[2];   // (64,) f32
    float* y = (float*)d_out;                 // (16, 64, 128, 128) f32

    cudaFuncSetAttribute(gemm_kernel, cudaFuncAttributeMaxDynamicSharedMemorySize,
                         GSM_TOTAL);

    wt_kernel<<<(NAB * 64 * 64 + 255) / 256, 256>>>(w);
    in_transform<<<4096, 256>>>(x);
    gemm_kernel<<<512, 256, GSM_TOTAL>>>(b, y);
}